// round 16
// baseline (speedup 1.0000x reference)
#include <cuda_runtime.h>
#include <cuda_bf16.h>
#include <cuda_fp16.h>
#include <math.h>
#include <stdint.h>

#define NB 4
#define C 256
#define P 2304          // 48*48
#define SIGMA 0.1f
#define INV_SIGMA 10.0f
#define EPS 1e-5f

#define KSEG 512          // stored K per row: [hi(256) | lo(256)]
#define NPROD 12           // products: per k: AhBh, AhBl, AlBh
#define TMT 96             // m tile
#define TNT 128            // n tile
#define A_CHUNK (TMT * 128)   // 12288
#define B_CHUNK (TNT * 128)   // 16384
#define SLOT_A 3
#define SLOT_B 4
#define SMEM_TOT (SLOT_A * A_CHUNK + SLOT_B * B_CHUNK)   // 102400

// ---------------- scratch ----------------
__device__ float g_mean[C];
__device__ __align__(16) __nv_bfloat16 g_Abf[(size_t)NB * P * KSEG];
__device__ __align__(16) __nv_bfloat16 g_Bbf[(size_t)NB * P * KSEG];
__device__ __align__(16) __half g_Dh[(size_t)NB * P * P];   // raw_dist, fp16 (~42.5 MB)
__device__ __align__(16) int   g_colMin[NB * P];
__device__ __align__(16) float g_colSum[NB * P];
__device__ __align__(16) float g_bArr[NB * P];
__device__ __align__(16) float g_cArr[NB * P];
__device__ float g_sampSum[NB];

// ---------------- helpers ----------------
__device__ __forceinline__ uint32_t s2u(const void* p) {
    uint32_t a;
    asm("{ .reg .u64 t; cvta.to.shared.u64 t, %1; cvt.u32.u64 %0, t; }" : "=r"(a) : "l"(p));
    return a;
}
__device__ __forceinline__ void cp16(uint32_t s, const void* g) {
    asm volatile("cp.async.cg.shared.global [%0], [%1], 16;" :: "r"(s), "l"(g));
}
#define CP_COMMIT() asm volatile("cp.async.commit_group;" ::: "memory")
#define CP_WAIT1()  asm volatile("cp.async.wait_group 1;" ::: "memory")

#define LDSM4(d, addr)                                                          \
    asm volatile("ldmatrix.sync.aligned.m8n8.x4.shared.b16 {%0,%1,%2,%3}, [%4];" \
        : "=r"((d)[0]), "=r"((d)[1]), "=r"((d)[2]), "=r"((d)[3]) : "r"(addr))

#define MMA16816(c, a, b0, b1)                                                  \
    asm volatile("mma.sync.aligned.m16n8k16.row.col.f32.bf16.bf16.f32 "          \
        "{%0,%1,%2,%3}, {%4,%5,%6,%7}, {%8,%9}, {%0,%1,%2,%3};"                  \
        : "+f"((c)[0]), "+f"((c)[1]), "+f"((c)[2]), "+f"((c)[3])                 \
        : "r"((a)[0]), "r"((a)[1]), "r"((a)[2]), "r"((a)[3]), "r"(b0), "r"(b1))

// ---------------- 1) per-channel mean (+ fused stat init) ----------------
__global__ void k_mean(const float* __restrict__ fT) {
    int gi = blockIdx.x * blockDim.x + threadIdx.x;
    if (gi < NB * P) {
        g_colMin[gi] = __float_as_int(3.0e38f);
        g_colSum[gi] = 0.f;
    }
    if (gi < NB) g_sampSum[gi] = 0.f;

    int c = blockIdx.x;
    float s = 0.f;
    for (int i = threadIdx.x; i < NB * P; i += blockDim.x) {
        int n = i / P, p = i - n * P;
        s += fT[((size_t)n * C + c) * P + p];
    }
    __shared__ float red[256];
    red[threadIdx.x] = s;
    __syncthreads();
    for (int o = 128; o > 0; o >>= 1) {
        if (threadIdx.x < o) red[threadIdx.x] += red[threadIdx.x + o];
        __syncthreads();
    }
    if (threadIdx.x == 0) g_mean[c] = red[0] * (1.0f / (NB * P));
}

// ---------------- 2) center + normalize + bf16 split pack ----------------
__global__ __launch_bounds__(256) void k_prep(const float* __restrict__ fT,
                                              const float* __restrict__ fI) {
    __shared__ float sT[C][17];
    __shared__ float sI[C][17];
    __shared__ float sm[C];
    __shared__ float part[2][256];
    __shared__ float invT[16], invI[16];
    int n = blockIdx.y, p0 = blockIdx.x * 16, tid = threadIdx.x;
    for (int c = tid; c < C; c += 256) sm[c] = g_mean[c];
    __syncthreads();
#pragma unroll
    for (int i = 0; i < 16; i++) {
        int idx = tid + i * 256;
        int c = idx >> 4, p = idx & 15;
        float m = sm[c];
        sT[c][p] = fT[((size_t)n * C + c) * P + p0 + p] - m;
        sI[c][p] = fI[((size_t)n * C + c) * P + p0 + p] - m;
    }
    __syncthreads();
    {
        int p = tid & 15, seg = tid >> 4;
        float aT = 0.f, aI = 0.f;
#pragma unroll
        for (int k = 0; k < 16; k++) {
            float x = sT[seg * 16 + k][p]; aT += x * x;
            float y = sI[seg * 16 + k][p]; aI += y * y;
        }
        part[0][tid] = aT;
        part[1][tid] = aI;
    }
    __syncthreads();
    if (tid < 16) {
        float aT = 0.f, aI = 0.f;
#pragma unroll
        for (int s = 0; s < 16; s++) { aT += part[0][s * 16 + tid]; aI += part[1][s * 16 + tid]; }
        invT[tid] = rsqrtf(aT);
        invI[tid] = rsqrtf(aI);
    }
    __syncthreads();
#pragma unroll 4
    for (int p = 0; p < 16; p++) {
        float vT = sT[tid][p] * invT[p];
        float vI = sI[tid][p] * invI[p];
        __nv_bfloat16 hT = __float2bfloat16(vT);
        __nv_bfloat16 lT = __float2bfloat16(vT - __bfloat162float(hT));
        __nv_bfloat16 hI = __float2bfloat16(vI);
        __nv_bfloat16 lI = __float2bfloat16(vI - __bfloat162float(hI));
        size_t base = ((size_t)n * P + p0 + p) * KSEG;
        g_Abf[base + tid]       = hT;
        g_Abf[base + 256 + tid] = lT;
        g_Bbf[base + tid]       = hI;
        g_Bbf[base + 256 + tid] = lI;
    }
}

// ---------------- 3) GEMM: 96x128 tiles, chunk-resident rings ---------------
__global__ __launch_bounds__(128, 2) void k_gemm() {
    extern __shared__ __align__(128) char smem[];
    const int tid = threadIdx.x;
    const int n  = blockIdx.z;
    const int m0 = blockIdx.y * TMT;
    const int j0 = blockIdx.x * TNT;
    const uint32_t sbA = s2u(smem);
    const uint32_t sbB = sbA + SLOT_A * A_CHUNK;

    const char* Ab = (const char*)g_Abf + ((size_t)n * P + m0) * (KSEG * 2);
    const char* Bb = (const char*)g_Bbf + ((size_t)n * P + j0) * (KSEG * 2);

    const int lrow = tid >> 3;       // 0..15
    const int lcol = tid & 7;
    auto load_chunkA = [&](uint32_t sdst, const char* gsrc) {
#pragma unroll
        for (int i = 0; i < 6; i++) {         // 96 rows
            int r = lrow + i * 16;
            int off = (r << 7) + ((lcol ^ (r & 7)) << 4);
            cp16(sdst + off, gsrc + (size_t)r * (KSEG * 2) + lcol * 16);
        }
    };
    auto load_chunkB = [&](uint32_t sdst, const char* gsrc) {
#pragma unroll
        for (int i = 0; i < 8; i++) {         // 128 rows
            int r = lrow + i * 16;
            int off = (r << 7) + ((lcol ^ (r & 7)) << 4);
            cp16(sdst + off, gsrc + (size_t)r * (KSEG * 2) + lcol * 16);
        }
    };

    const int warp = tid >> 5, lane = tid & 31;
    const int wm = warp & 1, wn = warp >> 1;    // 2(m) x 2(n) -> 48x64 warp tile
    const int aRow0 = wm * 48 + (lane & 15);
    const int bRow0 = wn * 64 + (lane & 15);
    const int gsel0 = lane >> 4;

    float acc[3][8][4];
#pragma unroll
    for (int mi = 0; mi < 3; mi++)
#pragma unroll
        for (int nj = 0; nj < 8; nj++)
#pragma unroll
            for (int q = 0; q < 4; q++) acc[mi][nj][q] = 0.f;

    uint32_t af[2][3][4], bf[2][4][4];
    auto load_frags = [&](uint32_t sA, uint32_t sB, int ks, int buf) {
        int gsel = ks * 2 + gsel0;
#pragma unroll
        for (int mi = 0; mi < 3; mi++) {
            int r = aRow0 + mi * 16;
            LDSM4(af[buf][mi], sA + (r << 7) + ((gsel ^ (r & 7)) << 4));
        }
#pragma unroll
        for (int bi = 0; bi < 4; bi++) {
            int r = bRow0 + bi * 16;
            LDSM4(bf[buf][bi], sB + (r << 7) + ((gsel ^ (r & 7)) << 4));
        }
    };

    // prologue: G1 = {Ah0 -> A0, Bh0 -> B0}, G2 = {Bl0 -> B1}
    load_chunkA(sbA, Ab);
    load_chunkB(sbB, Bb);
    CP_COMMIT();
    load_chunkB(sbB + B_CHUNK, Bb + 512);
    CP_COMMIT();

#pragma unroll
    for (int p = 0; p < NPROD; p++) {
        const int k = p / 3, r = p - 3 * k, k2 = k + 1;
        CP_WAIT1();
        __syncthreads();

        const int aS = ((r == 2) ? (2 * k + 1) : (2 * k)) % 3;
        const int bS = ((r == 1) ? (2 * k + 1) : (2 * k)) % 4;
        uint32_t sA = sbA + aS * A_CHUNK;
        uint32_t sB = sbB + bS * B_CHUNK;
        load_frags(sA, sB, 0, 0);   // hide LDSM latency under cp issue burst

        if (r == 0) {
            load_chunkA(sbA + ((2 * k + 1) % 3) * A_CHUNK, Ab + 512 + k * 128);          // Al_k
        } else if (r == 1) {
            if (k2 < 4) {
                load_chunkA(sbA + ((2 * k2) % 3) * A_CHUNK, Ab + k2 * 128);              // Ah_k2
                load_chunkB(sbB + ((2 * k2) % 4) * B_CHUNK, Bb + k2 * 128);              // Bh_k2
            }
        } else {
            if (k2 < 4)
                load_chunkB(sbB + ((2 * k2 + 1) % 4) * B_CHUNK, Bb + 512 + k2 * 128);    // Bl_k2
        }
        CP_COMMIT();

#pragma unroll
        for (int ks = 0; ks < 4; ks++) {
            int cur = ks & 1, nxt = cur ^ 1;
            if (ks < 3) load_frags(sA, sB, ks + 1, nxt);
#pragma unroll
            for (int mi = 0; mi < 3; mi++)
#pragma unroll
                for (int nj = 0; nj < 8; nj++)
                    MMA16816(acc[mi][nj], af[cur][mi],
                             bf[cur][nj >> 1][nj & 1], bf[cur][nj >> 1][(nj & 1) + 2]);
        }
    }

    // epilogue: raw = 0.5 - 0.5*dot; store fp16 + shuffle-reduced column-min
    const size_t Dbase = (size_t)n * P * P;
    float mnE[8], mnO[8];
#pragma unroll
    for (int nj = 0; nj < 8; nj++) { mnE[nj] = 3.0e38f; mnO[nj] = 3.0e38f; }

#pragma unroll
    for (int mi = 0; mi < 3; mi++) {
        int r0 = m0 + wm * 48 + mi * 16 + (lane >> 2);
        __half* rowp  = g_Dh + Dbase + (size_t)r0 * P;
        __half* rowp8 = rowp + (size_t)8 * P;
#pragma unroll
        for (int nj = 0; nj < 8; nj++) {
            int col = j0 + wn * 64 + nj * 8 + ((lane & 3) << 1);
            float f0 = 0.5f - 0.5f * acc[mi][nj][0];
            float f1 = 0.5f - 0.5f * acc[mi][nj][1];
            float f2 = 0.5f - 0.5f * acc[mi][nj][2];
            float f3 = 0.5f - 0.5f * acc[mi][nj][3];
            *(__half2*)(rowp  + col) = __floats2half2_rn(f0, f1);
            *(__half2*)(rowp8 + col) = __floats2half2_rn(f2, f3);
            mnE[nj] = fminf(mnE[nj], fminf(f0, f2));
            mnO[nj] = fminf(mnO[nj], fminf(f1, f3));
        }
    }
#pragma unroll
    for (int nj = 0; nj < 8; nj++) {
#pragma unroll
        for (int o = 4; o < 32; o <<= 1) {
            mnE[nj] = fminf(mnE[nj], __shfl_xor_sync(0xffffffffu, mnE[nj], o));
            mnO[nj] = fminf(mnO[nj], __shfl_xor_sync(0xffffffffu, mnO[nj], o));
        }
    }
    if (lane < 4) {
        int cb = n * P + j0 + wn * 64 + lane * 2;
#pragma unroll
        for (int nj = 0; nj < 8; nj++) {
            atomicMin(&g_colMin[cb + nj * 8],     __float_as_int(mnE[nj]));
            atomicMin(&g_colMin[cb + nj * 8 + 1], __float_as_int(mnO[nj]));
        }
    }
}

// ---------------- 4) column exp-sum (fp16 D, 4 cols/thread) ------------------
#define CS_TPB 192
#define CS_JT  768     // CS_TPB * 4
#define CS_ROWS 36     // 64 y-blocks -> 768 blocks total
__global__ __launch_bounds__(CS_TPB) void k_colsum() {
    int n = blockIdx.z;
    int j = blockIdx.x * CS_JT + threadIdx.x * 4;
    int p0 = blockIdx.y * CS_ROWS;
    int4 mi4 = *(const int4*)&g_colMin[n * P + j];
    float b0 = 1.0f / (SIGMA * (__int_as_float(mi4.x) + EPS));
    float b1 = 1.0f / (SIGMA * (__int_as_float(mi4.y) + EPS));
    float b2 = 1.0f / (SIGMA * (__int_as_float(mi4.z) + EPS));
    float b3 = 1.0f / (SIGMA * (__int_as_float(mi4.w) + EPS));
    const __half* base = g_Dh + (size_t)n * P * P + j;
    float s0 = 0.f, s1 = 0.f, s2 = 0.f, s3 = 0.f;
#pragma unroll 4
    for (int p = p0; p < p0 + CS_ROWS; p++) {
        uint2 v = *(const uint2*)(base + (size_t)p * P);
        float2 fa = __half22float2(*(__half2*)&v.x);
        float2 fb = __half22float2(*(__half2*)&v.y);
        s0 += __expf(INV_SIGMA - fa.x * b0);
        s1 += __expf(INV_SIGMA - fa.y * b1);
        s2 += __expf(INV_SIGMA - fb.x * b2);
        s3 += __expf(INV_SIGMA - fb.y * b3);
    }
    atomicAdd(&g_colSum[n * P + j],     s0);
    atomicAdd(&g_colSum[n * P + j + 1], s1);
    atomicAdd(&g_colSum[n * P + j + 2], s2);
    atomicAdd(&g_colSum[n * P + j + 3], s3);
}

// ---------------- 5) per-column constants (+ fused rowmax-scratch init) ------
__global__ void k_bc() {
    int i = blockIdx.x * blockDim.x + threadIdx.x;
    if (i >= NB * P) return;
    float m = __int_as_float(g_colMin[i]);
    g_bArr[i] = 1.0f / (SIGMA * (m + EPS));
    g_cArr[i] = INV_SIGMA - logf(g_colSum[i]);
    g_colMin[i] = 0x80000000;  // reset as ordered-int -inf for rowmax reuse
}

// ---------------- 6) row max (fp16 D, warp per full row, 8 cols/lane) --------
__global__ __launch_bounds__(512) void k_rowmax() {
    int R = blockIdx.x * 16 + (threadIdx.x >> 5);
    int lane = threadIdx.x & 31;
    int n = R / P, p = R - n * P;
    const __half* row = g_Dh + (size_t)n * P * P + (size_t)p * P;
    const float* bA = g_bArr + n * P;
    const float* cA = g_cArr + n * P;
    float m = -3.0e38f;
#pragma unroll
    for (int i = 0; i < P / 256; i++) {       // 9 iters, 8 cols/lane
        int j = lane * 8 + i * 256;
        uint4 rv = *(const uint4*)(row + j);
        float2 f0 = __half22float2(*(__half2*)&rv.x);
        float2 f1 = __half22float2(*(__half2*)&rv.y);
        float2 f2 = __half22float2(*(__half2*)&rv.z);
        float2 f3 = __half22float2(*(__half2*)&rv.w);
        float4 b0 = *(const float4*)(bA + j);
        float4 b1 = *(const float4*)(bA + j + 4);
        float4 c0 = *(const float4*)(cA + j);
        float4 c1 = *(const float4*)(cA + j + 4);
        m = fmaxf(m, fmaxf(fmaxf(c0.x - f0.x * b0.x, c0.y - f0.y * b0.y),
                           fmaxf(c0.z - f1.x * b0.z, c0.w - f1.y * b0.w)));
        m = fmaxf(m, fmaxf(fmaxf(c1.x - f2.x * b1.x, c1.y - f2.y * b1.y),
                           fmaxf(c1.z - f3.x * b1.z, c1.w - f3.y * b1.w)));
    }
#pragma unroll
    for (int o = 16; o; o >>= 1)
        m = fmaxf(m, __shfl_xor_sync(0xffffffffu, m, o));
    if (lane == 0) {
        int bits = __float_as_int(m);
        bits = (bits >= 0) ? bits : (bits ^ 0x7FFFFFFF);   // order-preserving encoding
        atomicMax(&g_colMin[n * P + p], bits);   // reuse g_colMin as row-max scratch
    }
}

// ---------------- 6b) finalize rows: exp(rowmax) -> per-sample sum ----------
__global__ void k_rowfin() {
    int i = blockIdx.x * blockDim.x + threadIdx.x;
    int n = i / P;
    int bits = g_colMin[i];
    bits = (bits >= 0) ? bits : (bits ^ 0x7FFFFFFF);
    float m = __int_as_float(bits);
    float e = expf(m);
#pragma unroll
    for (int o = 16; o; o >>= 1)
        e += __shfl_xor_sync(0xffffffffu, e, o);   // rows in a warp share n (P%32==0)
    if ((threadIdx.x & 31) == 0) atomicAdd(&g_sampSum[n], e);
}

// ---------------- 7) final ----------------
__global__ void k_final(float* __restrict__ out, int out_size) {
    float cxb[NB];
    float loss = 0.f;
#pragma unroll
    for (int n = 0; n < NB; n++) {
        cxb[n] = -logf(g_sampSum[n] * (1.0f / P));
        loss += cxb[n];
    }
    loss *= (1.0f / NB);
    if (out_size >= 1 + NB) {
        out[0] = loss;
        for (int n = 0; n < NB; n++) out[1 + n] = cxb[n];
        for (int i = 1 + NB; i < out_size; i++) out[i] = 0.f;
    } else if (out_size == NB) {
        for (int n = 0; n < NB; n++) out[n] = cxb[n];
    } else if (out_size >= 1) {
        out[0] = loss;
    }
}

// ---------------- launch ----------------
extern "C" void kernel_launch(void* const* d_in, const int* in_sizes, int n_in,
                              void* d_out, int out_size) {
    const float* fT = (const float*)d_in[0];
    const float* fI = (const float*)d_in[1];
    float* out = (float*)d_out;

    cudaFuncSetAttribute(k_gemm, cudaFuncAttributeMaxDynamicSharedMemorySize, SMEM_TOT);

    k_mean<<<C, 256>>>(fT);
    k_prep<<<dim3(P / 16, NB), 256>>>(fT, fI);
    k_gemm<<<dim3(P / TNT, P / TMT, NB), 128, SMEM_TOT>>>();
    k_colsum<<<dim3(P / CS_JT, P / CS_ROWS, NB), CS_TPB>>>();
    k_bc<<<(NB * P + 255) / 256, 256>>>();
    k_rowmax<<<(NB * P) / 16, 512>>>();
    k_rowfin<<<(NB * P) / 256, 256>>>();
    k_final<<<1, 1>>>(out, out_size);
}

// round 17
// speedup vs baseline: 1.0543x; 1.0543x over previous
#include <cuda_runtime.h>
#include <cuda_bf16.h>
#include <cuda_fp16.h>
#include <math.h>
#include <stdint.h>

#define NB 4
#define C 256
#define P 2304          // 48*48
#define SIGMA 0.1f
#define INV_SIGMA 10.0f
#define EPS 1e-5f

#define KSEG 512          // stored K per row: [hi(256) | lo(256)]
#define NPROD 12           // products: per k: AhBh, AhBl, AlBh
#define TMT 96             // m tile
#define TNT 128            // n tile
#define A_CHUNK (TMT * 128)   // 12288
#define B_CHUNK (TNT * 128)   // 16384
#define SLOT_A 3
#define SLOT_B 4
#define SMEM_TOT (SLOT_A * A_CHUNK + SLOT_B * B_CHUNK)   // 102400

// ---------------- scratch ----------------
__device__ float g_mean[C];
__device__ __align__(16) __nv_bfloat16 g_Abf[(size_t)NB * P * KSEG];
__device__ __align__(16) __nv_bfloat16 g_Bbf[(size_t)NB * P * KSEG];
__device__ __align__(16) __half g_Dh[(size_t)NB * P * P];   // raw_dist, fp16 (~42.5 MB)
__device__ __align__(16) int   g_colMin[NB * P];
__device__ __align__(16) float g_colSum[NB * P];
__device__ __align__(16) float g_bArr[NB * P];
__device__ __align__(16) float g_cArr[NB * P];
__device__ float g_sampSum[NB];

// ---------------- helpers ----------------
__device__ __forceinline__ uint32_t s2u(const void* p) {
    uint32_t a;
    asm("{ .reg .u64 t; cvta.to.shared.u64 t, %1; cvt.u32.u64 %0, t; }" : "=r"(a) : "l"(p));
    return a;
}
__device__ __forceinline__ void cp16(uint32_t s, const void* g) {
    asm volatile("cp.async.cg.shared.global [%0], [%1], 16;" :: "r"(s), "l"(g));
}
#define CP_COMMIT() asm volatile("cp.async.commit_group;" ::: "memory")
#define CP_WAIT1()  asm volatile("cp.async.wait_group 1;" ::: "memory")

#define LDSM4(d, addr)                                                          \
    asm volatile("ldmatrix.sync.aligned.m8n8.x4.shared.b16 {%0,%1,%2,%3}, [%4];" \
        : "=r"((d)[0]), "=r"((d)[1]), "=r"((d)[2]), "=r"((d)[3]) : "r"(addr))

#define MMA16816(c, a, b0, b1)                                                  \
    asm volatile("mma.sync.aligned.m16n8k16.row.col.f32.bf16.bf16.f32 "          \
        "{%0,%1,%2,%3}, {%4,%5,%6,%7}, {%8,%9}, {%0,%1,%2,%3};"                  \
        : "+f"((c)[0]), "+f"((c)[1]), "+f"((c)[2]), "+f"((c)[3])                 \
        : "r"((a)[0]), "r"((a)[1]), "r"((a)[2]), "r"((a)[3]), "r"(b0), "r"(b1))

// ---------------- 1) per-channel mean (+ fused stat init) ----------------
__global__ void k_mean(const float* __restrict__ fT) {
    int gi = blockIdx.x * blockDim.x + threadIdx.x;
    if (gi < NB * P) {
        g_colMin[gi] = __float_as_int(3.0e38f);
        g_colSum[gi] = 0.f;
    }
    if (gi < NB) g_sampSum[gi] = 0.f;

    int c = blockIdx.x;
    float s = 0.f;
    for (int i = threadIdx.x; i < NB * P; i += blockDim.x) {
        int n = i / P, p = i - n * P;
        s += fT[((size_t)n * C + c) * P + p];
    }
    __shared__ float red[256];
    red[threadIdx.x] = s;
    __syncthreads();
    for (int o = 128; o > 0; o >>= 1) {
        if (threadIdx.x < o) red[threadIdx.x] += red[threadIdx.x + o];
        __syncthreads();
    }
    if (threadIdx.x == 0) g_mean[c] = red[0] * (1.0f / (NB * P));
}

// ---------------- 2) center + normalize + bf16 split pack ----------------
__global__ __launch_bounds__(256) void k_prep(const float* __restrict__ fT,
                                              const float* __restrict__ fI) {
    __shared__ float sT[C][17];
    __shared__ float sI[C][17];
    __shared__ float sm[C];
    __shared__ float part[2][256];
    __shared__ float invT[16], invI[16];
    int n = blockIdx.y, p0 = blockIdx.x * 16, tid = threadIdx.x;
    for (int c = tid; c < C; c += 256) sm[c] = g_mean[c];
    __syncthreads();
#pragma unroll
    for (int i = 0; i < 16; i++) {
        int idx = tid + i * 256;
        int c = idx >> 4, p = idx & 15;
        float m = sm[c];
        sT[c][p] = fT[((size_t)n * C + c) * P + p0 + p] - m;
        sI[c][p] = fI[((size_t)n * C + c) * P + p0 + p] - m;
    }
    __syncthreads();
    {
        int p = tid & 15, seg = tid >> 4;
        float aT = 0.f, aI = 0.f;
#pragma unroll
        for (int k = 0; k < 16; k++) {
            float x = sT[seg * 16 + k][p]; aT += x * x;
            float y = sI[seg * 16 + k][p]; aI += y * y;
        }
        part[0][tid] = aT;
        part[1][tid] = aI;
    }
    __syncthreads();
    if (tid < 16) {
        float aT = 0.f, aI = 0.f;
#pragma unroll
        for (int s = 0; s < 16; s++) { aT += part[0][s * 16 + tid]; aI += part[1][s * 16 + tid]; }
        invT[tid] = rsqrtf(aT);
        invI[tid] = rsqrtf(aI);
    }
    __syncthreads();
#pragma unroll 4
    for (int p = 0; p < 16; p++) {
        float vT = sT[tid][p] * invT[p];
        float vI = sI[tid][p] * invI[p];
        __nv_bfloat16 hT = __float2bfloat16(vT);
        __nv_bfloat16 lT = __float2bfloat16(vT - __bfloat162float(hT));
        __nv_bfloat16 hI = __float2bfloat16(vI);
        __nv_bfloat16 lI = __float2bfloat16(vI - __bfloat162float(hI));
        size_t base = ((size_t)n * P + p0 + p) * KSEG;
        g_Abf[base + tid]       = hT;
        g_Abf[base + 256 + tid] = lT;
        g_Bbf[base + tid]       = hI;
        g_Bbf[base + 256 + tid] = lI;
    }
}

// ---------------- 3) GEMM: 96x128 tiles, rings + smem-staged fp16 epilogue ---
__global__ __launch_bounds__(128, 2) void k_gemm() {
    extern __shared__ __align__(128) char smem[];
    const int tid = threadIdx.x;
    const int n  = blockIdx.z;
    const int m0 = blockIdx.y * TMT;
    const int j0 = blockIdx.x * TNT;
    const uint32_t sbA = s2u(smem);
    const uint32_t sbB = sbA + SLOT_A * A_CHUNK;

    const char* Ab = (const char*)g_Abf + ((size_t)n * P + m0) * (KSEG * 2);
    const char* Bb = (const char*)g_Bbf + ((size_t)n * P + j0) * (KSEG * 2);

    const int lrow = tid >> 3;       // 0..15
    const int lcol = tid & 7;
    auto load_chunkA = [&](uint32_t sdst, const char* gsrc) {
#pragma unroll
        for (int i = 0; i < 6; i++) {         // 96 rows
            int r = lrow + i * 16;
            int off = (r << 7) + ((lcol ^ (r & 7)) << 4);
            cp16(sdst + off, gsrc + (size_t)r * (KSEG * 2) + lcol * 16);
        }
    };
    auto load_chunkB = [&](uint32_t sdst, const char* gsrc) {
#pragma unroll
        for (int i = 0; i < 8; i++) {         // 128 rows
            int r = lrow + i * 16;
            int off = (r << 7) + ((lcol ^ (r & 7)) << 4);
            cp16(sdst + off, gsrc + (size_t)r * (KSEG * 2) + lcol * 16);
        }
    };

    const int warp = tid >> 5, lane = tid & 31;
    const int wm = warp & 1, wn = warp >> 1;    // 2(m) x 2(n) -> 48x64 warp tile
    const int aRow0 = wm * 48 + (lane & 15);
    const int bRow0 = wn * 64 + (lane & 15);
    const int gsel0 = lane >> 4;

    float acc[3][8][4];
#pragma unroll
    for (int mi = 0; mi < 3; mi++)
#pragma unroll
        for (int nj = 0; nj < 8; nj++)
#pragma unroll
            for (int q = 0; q < 4; q++) acc[mi][nj][q] = 0.f;

    uint32_t af[2][3][4], bf[2][4][4];
    auto load_frags = [&](uint32_t sA, uint32_t sB, int ks, int buf) {
        int gsel = ks * 2 + gsel0;
#pragma unroll
        for (int mi = 0; mi < 3; mi++) {
            int r = aRow0 + mi * 16;
            LDSM4(af[buf][mi], sA + (r << 7) + ((gsel ^ (r & 7)) << 4));
        }
#pragma unroll
        for (int bi = 0; bi < 4; bi++) {
            int r = bRow0 + bi * 16;
            LDSM4(bf[buf][bi], sB + (r << 7) + ((gsel ^ (r & 7)) << 4));
        }
    };

    // prologue: G1 = {Ah0 -> A0, Bh0 -> B0}, G2 = {Bl0 -> B1}
    load_chunkA(sbA, Ab);
    load_chunkB(sbB, Bb);
    CP_COMMIT();
    load_chunkB(sbB + B_CHUNK, Bb + 512);
    CP_COMMIT();

#pragma unroll
    for (int p = 0; p < NPROD; p++) {
        const int k = p / 3, r = p - 3 * k, k2 = k + 1;
        CP_WAIT1();
        __syncthreads();

        const int aS = ((r == 2) ? (2 * k + 1) : (2 * k)) % 3;
        const int bS = ((r == 1) ? (2 * k + 1) : (2 * k)) % 4;
        uint32_t sA = sbA + aS * A_CHUNK;
        uint32_t sB = sbB + bS * B_CHUNK;
        load_frags(sA, sB, 0, 0);   // hide LDSM latency under cp issue burst

        if (r == 0) {
            load_chunkA(sbA + ((2 * k + 1) % 3) * A_CHUNK, Ab + 512 + k * 128);          // Al_k
        } else if (r == 1) {
            if (k2 < 4) {
                load_chunkA(sbA + ((2 * k2) % 3) * A_CHUNK, Ab + k2 * 128);              // Ah_k2
                load_chunkB(sbB + ((2 * k2) % 4) * B_CHUNK, Bb + k2 * 128);              // Bh_k2
            }
        } else {
            if (k2 < 4)
                load_chunkB(sbB + ((2 * k2 + 1) % 4) * B_CHUNK, Bb + 512 + k2 * 128);    // Bl_k2
        }
        CP_COMMIT();

#pragma unroll
        for (int ks = 0; ks < 4; ks++) {
            int cur = ks & 1, nxt = cur ^ 1;
            if (ks < 3) load_frags(sA, sB, ks + 1, nxt);
#pragma unroll
            for (int mi = 0; mi < 3; mi++)
#pragma unroll
                for (int nj = 0; nj < 8; nj++)
                    MMA16816(acc[mi][nj], af[cur][mi],
                             bf[cur][nj >> 1][nj & 1], bf[cur][nj >> 1][(nj & 1) + 2]);
        }
    }

    // ---------------- epilogue: stage fp16 tile in smem, coalesced store -----
    const size_t Dbase = (size_t)n * P * P;
    float mnE[8], mnO[8];
#pragma unroll
    for (int nj = 0; nj < 8; nj++) { mnE[nj] = 3.0e38f; mnO[nj] = 3.0e38f; }

    __syncthreads();                       // mainloop smem reads complete
    __half* stile = (__half*)smem;         // 96 x 128 fp16 = 24 KB

#pragma unroll
    for (int mi = 0; mi < 3; mi++) {
        int r0 = wm * 48 + mi * 16 + (lane >> 2);   // tile-local row
#pragma unroll
        for (int nj = 0; nj < 8; nj++) {
            int col = wn * 64 + nj * 8 + ((lane & 3) << 1);   // tile-local col
            float f0 = 0.5f - 0.5f * acc[mi][nj][0];
            float f1 = 0.5f - 0.5f * acc[mi][nj][1];
            float f2 = 0.5f - 0.5f * acc[mi][nj][2];
            float f3 = 0.5f - 0.5f * acc[mi][nj][3];
            *(__half2*)(stile + r0 * 128 + col)       = __floats2half2_rn(f0, f1);
            *(__half2*)(stile + (r0 + 8) * 128 + col) = __floats2half2_rn(f2, f3);
            mnE[nj] = fminf(mnE[nj], fminf(f0, f2));
            mnO[nj] = fminf(mnO[nj], fminf(f1, f3));
        }
    }
#pragma unroll
    for (int nj = 0; nj < 8; nj++) {
#pragma unroll
        for (int o = 4; o < 32; o <<= 1) {
            mnE[nj] = fminf(mnE[nj], __shfl_xor_sync(0xffffffffu, mnE[nj], o));
            mnO[nj] = fminf(mnO[nj], __shfl_xor_sync(0xffffffffu, mnO[nj], o));
        }
    }
    if (lane < 4) {
        int cb = n * P + j0 + wn * 64 + lane * 2;
#pragma unroll
        for (int nj = 0; nj < 8; nj++) {
            atomicMin(&g_colMin[cb + nj * 8],     __float_as_int(mnE[nj]));
            atomicMin(&g_colMin[cb + nj * 8 + 1], __float_as_int(mnO[nj]));
        }
    }
    __syncthreads();
    // coalesced copy out: 96 rows x 16 uint4 = 1536, 12 per thread
#pragma unroll
    for (int i = 0; i < 12; i++) {
        int idx = tid + i * 128;
        int row = idx >> 4, c16 = idx & 15;
        uint4 v = *(const uint4*)(stile + row * 128 + c16 * 8);
        *(uint4*)(g_Dh + Dbase + (size_t)(m0 + row) * P + j0 + c16 * 8) = v;
    }
}

// ---------------- 4) column exp-sum (fp16 D, 4 cols/thread) ------------------
#define CS_TPB 192
#define CS_JT  768     // CS_TPB * 4
#define CS_ROWS 36     // 64 y-blocks -> 768 blocks total
__global__ __launch_bounds__(CS_TPB) void k_colsum() {
    int n = blockIdx.z;
    int j = blockIdx.x * CS_JT + threadIdx.x * 4;
    int p0 = blockIdx.y * CS_ROWS;
    int4 mi4 = *(const int4*)&g_colMin[n * P + j];
    float b0 = 1.0f / (SIGMA * (__int_as_float(mi4.x) + EPS));
    float b1 = 1.0f / (SIGMA * (__int_as_float(mi4.y) + EPS));
    float b2 = 1.0f / (SIGMA * (__int_as_float(mi4.z) + EPS));
    float b3 = 1.0f / (SIGMA * (__int_as_float(mi4.w) + EPS));
    const __half* base = g_Dh + (size_t)n * P * P + j;
    float s0 = 0.f, s1 = 0.f, s2 = 0.f, s3 = 0.f;
#pragma unroll 4
    for (int p = p0; p < p0 + CS_ROWS; p++) {
        uint2 v = *(const uint2*)(base + (size_t)p * P);
        float2 fa = __half22float2(*(__half2*)&v.x);
        float2 fb = __half22float2(*(__half2*)&v.y);
        s0 += __expf(INV_SIGMA - fa.x * b0);
        s1 += __expf(INV_SIGMA - fa.y * b1);
        s2 += __expf(INV_SIGMA - fb.x * b2);
        s3 += __expf(INV_SIGMA - fb.y * b3);
    }
    atomicAdd(&g_colSum[n * P + j],     s0);
    atomicAdd(&g_colSum[n * P + j + 1], s1);
    atomicAdd(&g_colSum[n * P + j + 2], s2);
    atomicAdd(&g_colSum[n * P + j + 3], s3);
}

// ---------------- 5) per-column constants (+ fused rowmax-scratch init) ------
__global__ void k_bc() {
    int i = blockIdx.x * blockDim.x + threadIdx.x;
    if (i >= NB * P) return;
    float m = __int_as_float(g_colMin[i]);
    g_bArr[i] = 1.0f / (SIGMA * (m + EPS));
    g_cArr[i] = INV_SIGMA - logf(g_colSum[i]);
    g_colMin[i] = 0x80000000;  // reset as ordered-int -inf for rowmax reuse
}

// ---------------- 6) row max (fp16 D, half-row per warp) ----------------
__global__ __launch_bounds__(512) void k_rowmax() {
    int w = blockIdx.x * 16 + (threadIdx.x >> 5);  // 2 warps per row
    int lane = threadIdx.x & 31;
    int R = w >> 1, half = w & 1;
    int n = R / P, p = R - n * P;
    const int jbase = half * (P / 2);
    const __half* row = g_Dh + (size_t)n * P * P + (size_t)p * P + jbase;
    const float* bA = g_bArr + n * P + jbase;
    const float* cA = g_cArr + n * P + jbase;
    float m = -3.0e38f;
#pragma unroll
    for (int i = 0; i < P / 256; i++) {       // 9 iters per half-row
        int j = lane * 4 + i * 128;
        uint2 rv = *(const uint2*)(row + j);
        float2 fa = __half22float2(*(__half2*)&rv.x);
        float2 fb = __half22float2(*(__half2*)&rv.y);
        float4 b = *(const float4*)(bA + j);
        float4 c = *(const float4*)(cA + j);
        m = fmaxf(m, fmaxf(fmaxf(c.x - fa.x * b.x, c.y - fa.y * b.y),
                           fmaxf(c.z - fb.x * b.z, c.w - fb.y * b.w)));
    }
#pragma unroll
    for (int o = 16; o; o >>= 1)
        m = fmaxf(m, __shfl_xor_sync(0xffffffffu, m, o));
    if (lane == 0) {
        int bits = __float_as_int(m);
        bits = (bits >= 0) ? bits : (bits ^ 0x7FFFFFFF);   // order-preserving encoding
        atomicMax(&g_colMin[n * P + p], bits);   // reuse g_colMin as row-max scratch
    }
}

// ---------------- 6b) finalize rows: exp(rowmax) -> per-sample sum ----------
__global__ void k_rowfin() {
    int i = blockIdx.x * blockDim.x + threadIdx.x;
    int n = i / P;
    int bits = g_colMin[i];
    bits = (bits >= 0) ? bits : (bits ^ 0x7FFFFFFF);
    float m = __int_as_float(bits);
    float e = expf(m);
#pragma unroll
    for (int o = 16; o; o >>= 1)
        e += __shfl_xor_sync(0xffffffffu, e, o);   // rows in a warp share n (P%32==0)
    if ((threadIdx.x & 31) == 0) atomicAdd(&g_sampSum[n], e);
}

// ---------------- 7) final ----------------
__global__ void k_final(float* __restrict__ out, int out_size) {
    float cxb[NB];
    float loss = 0.f;
#pragma unroll
    for (int n = 0; n < NB; n++) {
        cxb[n] = -logf(g_sampSum[n] * (1.0f / P));
        loss += cxb[n];
    }
    loss *= (1.0f / NB);
    if (out_size >= 1 + NB) {
        out[0] = loss;
        for (int n = 0; n < NB; n++) out[1 + n] = cxb[n];
        for (int i = 1 + NB; i < out_size; i++) out[i] = 0.f;
    } else if (out_size == NB) {
        for (int n = 0; n < NB; n++) out[n] = cxb[n];
    } else if (out_size >= 1) {
        out[0] = loss;
    }
}

// ---------------- launch ----------------
extern "C" void kernel_launch(void* const* d_in, const int* in_sizes, int n_in,
                              void* d_out, int out_size) {
    const float* fT = (const float*)d_in[0];
    const float* fI = (const float*)d_in[1];
    float* out = (float*)d_out;

    cudaFuncSetAttribute(k_gemm, cudaFuncAttributeMaxDynamicSharedMemorySize, SMEM_TOT);

    k_mean<<<C, 256>>>(fT);
    k_prep<<<dim3(P / 16, NB), 256>>>(fT, fI);
    k_gemm<<<dim3(P / TNT, P / TMT, NB), 128, SMEM_TOT>>>();
    k_colsum<<<dim3(P / CS_JT, P / CS_ROWS, NB), CS_TPB>>>();
    k_bc<<<(NB * P + 255) / 256, 256>>>();
    k_rowmax<<<(NB * P * 2) / 16, 512>>>();
    k_rowfin<<<(NB * P) / 256, 256>>>();
    k_final<<<1, 1>>>(out, out_size);
}